// round 9
// baseline (speedup 1.0000x reference)
#include <cuda_runtime.h>
#include <cuda_bf16.h>
#include <cstdint>

// ---------------------------------------------------------------------------
// Problem constants
// ---------------------------------------------------------------------------
#define NTOK  4096          // 8 * 512 tokens (t=0 dropped)
#define DDIM  768
#define KCENT 8192

#define BM 128
#define BN 128
#define BK 64               // 64 int8 = 64B rows
#define KCHUNKS (DDIM / BK) // 12
#define NSTAGE 4
#define DELTA 20.0f         // prune threshold (int8 quant err std ~1.1 -> 18 sigma)
#define NREG 128            // 64-centroid regions per token
#define CAP 512             // extras capacity per token

#define QSCALE (127.0f / 6.0f)
#define DSC (2.0f * (6.0f / 127.0f) * (6.0f / 127.0f))   // dist = cn - DSC*acc

#define ASTAGE (128 * 64)               // 8KB
#define BSTAGE (128 * 64)               // 8KB
#define STAGE_BYTES (ASTAGE + BSTAGE)   // 16KB
#define SMEM_BYTES (NSTAGE * STAGE_BYTES) // 64KB dynamic

// ---------------------------------------------------------------------------
// Scratch (allocation-free: __device__ globals)
// ---------------------------------------------------------------------------
__device__ float g_cnorm[KCENT];
__device__ __align__(16) signed char gA8[(size_t)NTOK * DDIM];    // int8(rep)
__device__ __align__(16) signed char gB8[(size_t)KCENT * DDIM];   // int8(cent)
__device__ float g_pd[(size_t)NTOK * NREG];      // per-region approx min
__device__ int   g_pi[(size_t)NTOK * NREG];      // per-region approx argmin
__device__ int   g_cnt[NTOK];                    // extras counter
__device__ float g_cv[(size_t)NTOK * CAP];       // extras approx value
__device__ int   g_ci[(size_t)NTOK * CAP];       // extras index

// ---------------------------------------------------------------------------
// Helpers
// ---------------------------------------------------------------------------
__device__ __forceinline__ uint32_t smem_u32(const void* p) {
    uint32_t a;
    asm("{ .reg .u64 t; cvta.to.shared.u64 t, %1; cvt.u32.u64 %0, t; }" : "=r"(a) : "l"(p));
    return a;
}

// Swizzled offset for (row, 16B-chunk) in a row-major 64B-row buffer.
// Conflict-free for cp.async writes and ldmatrix 8-row phases.
__device__ __forceinline__ uint32_t swoff(int row, int chunk) {
    return (uint32_t)(row * 64 + ((chunk ^ ((row >> 1) & 3)) << 4));
}

#define CP_ASYNC16(dst, src) \
    asm volatile("cp.async.cg.shared.global [%0], [%1], 16;" :: "r"(dst), "l"(src) : "memory")
#define CP_COMMIT() asm volatile("cp.async.commit_group;" ::: "memory")
#define CP_WAIT(n)  asm volatile("cp.async.wait_group %0;" :: "n"(n) : "memory")

__device__ __forceinline__ void ldsm4(uint32_t* r, uint32_t addr) {
    asm volatile("ldmatrix.sync.aligned.m8n8.x4.shared.b16 {%0,%1,%2,%3}, [%4];"
                 : "=r"(r[0]), "=r"(r[1]), "=r"(r[2]), "=r"(r[3]) : "r"(addr));
}

__device__ __forceinline__ void mma16832(int* c, const uint32_t* a, const uint32_t* b) {
    asm volatile(
        "mma.sync.aligned.m16n8k32.row.col.s32.s8.s8.s32 "
        "{%0,%1,%2,%3}, {%4,%5,%6,%7}, {%8,%9}, {%0,%1,%2,%3};"
        : "+r"(c[0]), "+r"(c[1]), "+r"(c[2]), "+r"(c[3])
        : "r"(a[0]), "r"(a[1]), "r"(a[2]), "r"(a[3]), "r"(b[0]), "r"(b[1]));
}

__device__ __forceinline__ int q8(float x) {
    x = fminf(fmaxf(x, -6.f), 6.f) * QSCALE;
    return __float2int_rn(x);
}

__device__ __forceinline__ uint32_t pack4(float a, float b, float c, float d) {
    return (uint32_t)(q8(a) & 255) | ((uint32_t)(q8(b) & 255) << 8) |
           ((uint32_t)(q8(c) & 255) << 16) | ((uint32_t)(q8(d) & 255) << 24);
}

// ---------------------------------------------------------------------------
// Init / conversion kernels
// ---------------------------------------------------------------------------
__global__ void zero_cnt() {
    g_cnt[blockIdx.x * 256 + threadIdx.x] = 0;
}

// rep (dropping t=0 rows) -> dense [4096 x 768] int8
__global__ void conv_rep_q(const float* __restrict__ rep) {
    int i = blockIdx.x * 256 + threadIdx.x;           // over NTOK*DDIM/4
    int row = i / (DDIM / 4);
    int c4  = i % (DDIM / 4);
    int srow = row + (row >> 9) + 1;                  // b*513 + t + 1
    float4 v = ((const float4*)rep)[(size_t)srow * (DDIM / 4) + c4];
    ((uint32_t*)gA8)[i] = pack4(v.x, v.y, v.z, v.w);
}

// centroids -> int8, fused with fp32 squared-norm (one warp per centroid)
__global__ void conv_cent_q(const float* __restrict__ cent) {
    int k = blockIdx.x * 8 + (threadIdx.x >> 5);
    int lane = threadIdx.x & 31;
    const float4* src = (const float4*)(cent + (size_t)k * DDIM);
    uint32_t* dst = (uint32_t*)(gB8 + (size_t)k * DDIM);
    float s = 0.f;
#pragma unroll
    for (int j = 0; j < 6; ++j) {                     // 6*32 = 192 float4 = 768
        int q = lane + 32 * j;
        float4 v = src[q];
        dst[q] = pack4(v.x, v.y, v.z, v.w);
        s += v.x * v.x + v.y * v.y + v.z * v.z + v.w * v.w;
    }
#pragma unroll
    for (int off = 16; off; off >>= 1) s += __shfl_down_sync(0xffffffffu, s, off);
    if (lane == 0) g_cnorm[k] = s;
}

// ---------------------------------------------------------------------------
// Phase 1: int8 GEMM; epilogue emits per-region (min, argmin) + extras.
// Grid (32, 64), 256 threads. Warp grid 4(m) x 2(n): warp tile 32 x 64.
// 4-stage cp.async pipeline, single __syncthreads per k-iter.
// ---------------------------------------------------------------------------
__global__ __launch_bounds__(256, 2) void vq_gemm() {
    extern __shared__ __align__(16) char smem[];
    const uint32_t sb = smem_u32(smem);

    const int tid  = threadIdx.x;
    const int wid  = tid >> 5;
    const int lane = tid & 31;
    const int warp_m = wid & 3;     // 4 rows of warps (32 rows each)
    const int warp_n = wid >> 2;    // 2 cols of warps (64 cols each)
    const int mBase = blockIdx.x * BM;
    const int nBase = blockIdx.y * BN;

    auto load_stage = [&](int k0, int st) {
        const uint32_t base = sb + st * STAGE_BYTES;
#pragma unroll
        for (int t = 0; t < 4; ++t) {
            int l = tid + t * 256;            // 0..1023
            int part = l >> 9;                // 0: A, 1: B (512 chunks each)
            int e = l & 511;
            int row = e >> 2, ch = e & 3;
            const signed char* src = part
                ? &gB8[(size_t)(nBase + row) * DDIM + k0 + ch * 16]
                : &gA8[(size_t)(mBase + row) * DDIM + k0 + ch * 16];
            CP_ASYNC16(base + part * ASTAGE + swoff(row, ch), src);
        }
    };

    int acc[2][8][4];
#pragma unroll
    for (int mt = 0; mt < 2; ++mt)
#pragma unroll
        for (int nt = 0; nt < 8; ++nt)
#pragma unroll
            for (int i = 0; i < 4; ++i) acc[mt][nt][i] = 0;

    // ldmatrix lane address components (16B chunk granularity)
    const int aRow = warp_m * 32 + (lane & 15);          // + mt*16
    const int aCh  = lane >> 4;                          // chunk within k32 pair
    const int bRow = warp_n * 64 + (lane & 7) + ((lane >> 4) << 3);  // + nt2*16
    const int bCh  = (lane >> 3) & 1;

    load_stage(0, 0);      CP_COMMIT();
    load_stage(BK, 1);     CP_COMMIT();
    load_stage(2 * BK, 2); CP_COMMIT();

    for (int it = 0; it < KCHUNKS; ++it) {
        CP_WAIT(2);                      // stage 'it' data arrived (this thread)
        __syncthreads();                 // all threads arrived; stage it-1 consumed
        if (it + 3 < KCHUNKS) {
            load_stage((it + 3) * BK, (it + 3) % NSTAGE);
            CP_COMMIT();
        }
        const uint32_t stA = sb + (it % NSTAGE) * STAGE_BYTES;
        const uint32_t stB = stA + ASTAGE;

#pragma unroll
        for (int ks = 0; ks < 2; ++ks) {  // two k32 steps per 64B row
            uint32_t afr[2][4];
            uint32_t bfr[8][2];
#pragma unroll
            for (int mt = 0; mt < 2; ++mt)
                ldsm4(afr[mt], stA + swoff(aRow + mt * 16, ks * 2 + aCh));
#pragma unroll
            for (int nt2 = 0; nt2 < 4; ++nt2) {
                uint32_t r[4];
                ldsm4(r, stB + swoff(bRow + nt2 * 16, ks * 2 + bCh));
                bfr[nt2 * 2][0]     = r[0];
                bfr[nt2 * 2][1]     = r[1];
                bfr[nt2 * 2 + 1][0] = r[2];
                bfr[nt2 * 2 + 1][1] = r[3];
            }
#pragma unroll
            for (int mt = 0; mt < 2; ++mt)
#pragma unroll
                for (int nt = 0; nt < 8; ++nt)
                    mma16832(acc[mt][nt], afr[mt], bfr[nt]);
        }
    }

    // ---- Epilogue: per-row region min/argmin + extras within DELTA ----
    const int groupID = lane >> 2;
    const int tIdx    = lane & 3;
    const int colBase = nBase + warp_n * 64;
    const int region  = blockIdx.y * 2 + warp_n;

    float cn[8][2];
#pragma unroll
    for (int nt = 0; nt < 8; ++nt) {
        cn[nt][0] = __ldg(&g_cnorm[colBase + nt * 8 + tIdx * 2 + 0]);
        cn[nt][1] = __ldg(&g_cnorm[colBase + nt * 8 + tIdx * 2 + 1]);
    }

#pragma unroll
    for (int mt = 0; mt < 2; ++mt)
#pragma unroll
        for (int rh = 0; rh < 2; ++rh) {
            const int row = mBase + warp_m * 32 + mt * 16 + rh * 8 + groupID;
            float dv[8][2];
            float best = 3.4e38f;
            int bidx = 0;
#pragma unroll
            for (int nt = 0; nt < 8; ++nt)
#pragma unroll
                for (int jj = 0; jj < 2; ++jj) {
                    float d = cn[nt][jj] - DSC * (float)acc[mt][nt][rh * 2 + jj];
                    dv[nt][jj] = d;
                    int gi = colBase + nt * 8 + tIdx * 2 + jj;
                    if (d < best) { best = d; bidx = gi; }
                }
            // quad reduce (lanes groupID*4 + tIdx); all lanes converge
#pragma unroll
            for (int x = 1; x < 4; x <<= 1) {
                float od = __shfl_xor_sync(0xffffffffu, best, x);
                int   oi = __shfl_xor_sync(0xffffffffu, bidx, x);
                if (od < best || (od == best && oi < bidx)) { best = od; bidx = oi; }
            }
            if (tIdx == 0) {
                g_pd[(size_t)row * NREG + region] = best;
                g_pi[(size_t)row * NREG + region] = bidx;
            }
            // extras: values within DELTA of region min (excluding argmin)
            const float lim = best + DELTA;
#pragma unroll
            for (int nt = 0; nt < 8; ++nt)
#pragma unroll
                for (int jj = 0; jj < 2; ++jj) {
                    int gi = colBase + nt * 8 + tIdx * 2 + jj;
                    if (dv[nt][jj] <= lim && gi != bidx) {
                        int c = atomicAdd(&g_cnt[row], 1);
                        if (c < CAP) {
                            g_cv[(size_t)row * CAP + c] = dv[nt][jj];
                            g_ci[(size_t)row * CAP + c] = gi;
                        }
                    }
                }
        }
}

// ---------------------------------------------------------------------------
// Phase 2: per-token threshold + exact fp32 rescue + gather.
// One 128-thread block per token.
// Output layout: [tokens(4096) | quantized(4096*768)] float32.
// ---------------------------------------------------------------------------
#define MAXC 384
__global__ __launch_bounds__(128) void finalize(const float* __restrict__ rep,
                                                const float* __restrict__ cent,
                                                float* __restrict__ out) {
    __shared__ __align__(16) float srep[DDIM];
    __shared__ float wred[4];
    __shared__ float sthr;
    __shared__ int scand[MAXC];
    __shared__ int scn;
    __shared__ unsigned long long sbest;

    const int i = blockIdx.x;
    const int t = threadIdx.x;
    const int warpid = t >> 5;
    const int lane = t & 31;

    // rep row -> smem
    const int srow = i + (i >> 9) + 1;
    const float4* repv = (const float4*)(rep + (size_t)srow * DDIM);
#pragma unroll
    for (int q = 0; q < 2; ++q)
        if (t + q * 128 < DDIM / 4) ((float4*)srep)[t + q * 128] = repv[t + q * 128];
    if (t == 0) { scn = 0; sbest = ~0ull; }

    // dense region mins (coalesced: [token][region])
    const float dmin = g_pd[(size_t)i * NREG + t];
    float m = dmin;
#pragma unroll
    for (int off = 16; off; off >>= 1)
        m = fminf(m, __shfl_xor_sync(0xffffffffu, m, off));
    if (lane == 0) wred[warpid] = m;
    __syncthreads();
    if (t == 0) {
        float mm = fminf(fminf(wred[0], wred[1]), fminf(wred[2], wred[3]));
        sthr = mm + DELTA;
    }
    __syncthreads();
    const float thr = sthr;

    // collect candidates
    if (dmin <= thr) {
        int c = atomicAdd(&scn, 1);
        if (c < MAXC) scand[c] = g_pi[(size_t)i * NREG + t];
    }
    int ec = g_cnt[i];
    if (ec > CAP) ec = CAP;
    for (int e = t; e < ec; e += 128)
        if (g_cv[(size_t)i * CAP + e] <= thr) {
            int c = atomicAdd(&scn, 1);
            if (c < MAXC) scand[c] = g_ci[(size_t)i * CAP + e];
        }
    __syncthreads();

    // exact fp32 rescue, one candidate per warp round-robin
    int nc = scn < MAXC ? scn : MAXC;
    for (int c = warpid; c < nc; c += 4) {
        const int k = scand[c];
        const float4* c4 = (const float4*)(cent + (size_t)k * DDIM);
        float s0 = 0.f, s1 = 0.f, s2 = 0.f, s3 = 0.f;
#pragma unroll
        for (int q = lane; q < DDIM / 4; q += 32) {
            float4 cv = __ldg(&c4[q]);
            float4 rv = ((const float4*)srep)[q];
            s0 = fmaf(rv.x, cv.x, s0);
            s1 = fmaf(rv.y, cv.y, s1);
            s2 = fmaf(rv.z, cv.z, s2);
            s3 = fmaf(rv.w, cv.w, s3);
        }
        float s = (s0 + s1) + (s2 + s3);
#pragma unroll
        for (int off = 16; off; off >>= 1) s += __shfl_xor_sync(0xffffffffu, s, off);
        if (lane == 0) {
            float d = __ldg(&g_cnorm[k]) - 2.f * s;
            unsigned int u = __float_as_uint(d);
            unsigned int key = (u & 0x80000000u) ? ~u : (u | 0x80000000u);
            unsigned long long pk = ((unsigned long long)key << 32) | (unsigned int)k;
            atomicMin(&sbest, pk);
        }
    }
    __syncthreads();

    const int kbest = (int)(sbest & 0xffffffffu);
    if (t == 0) out[i] = (float)kbest;
    const float4* src = (const float4*)(cent + (size_t)kbest * DDIM);
    float4* dst = (float4*)(out + NTOK + (size_t)i * DDIM);
#pragma unroll
    for (int q = 0; q < 2; ++q)
        if (t + q * 128 < DDIM / 4) dst[t + q * 128] = src[t + q * 128];
}

// ---------------------------------------------------------------------------
extern "C" void kernel_launch(void* const* d_in, const int* in_sizes, int n_in,
                              void* d_out, int out_size) {
    const float* rep  = (const float*)d_in[0];   // [8,513,768]
    const float* cent = (const float*)d_in[1];   // [8192,768]
    float* out = (float*)d_out;

    cudaFuncSetAttribute(vq_gemm, cudaFuncAttributeMaxDynamicSharedMemorySize,
                         SMEM_BYTES);

    zero_cnt<<<NTOK / 256, 256>>>();
    conv_rep_q<<<(size_t)NTOK * DDIM / 4 / 256, 256>>>(rep);
    conv_cent_q<<<KCENT / 8, 256>>>(cent);

    dim3 g(NTOK / BM, KCENT / BN);
    vq_gemm<<<g, 256, SMEM_BYTES>>>();

    finalize<<<NTOK, 128>>>(rep, cent, out);
}

// round 10
// speedup vs baseline: 2.1779x; 2.1779x over previous
#include <cuda_runtime.h>
#include <cuda_bf16.h>
#include <cstdint>

// ---------------------------------------------------------------------------
// Problem constants
// ---------------------------------------------------------------------------
#define NTOK  4096          // 8 * 512 tokens (t=0 dropped)
#define DDIM  768
#define KCENT 8192

#define BM 128
#define BN 128
#define BK 64               // 64 bf16 = 128B rows (SW128)
#define KCHUNKS (DDIM / BK) // 12
#define NSTAGE 3
#define DELTA 8.0f          // prune threshold (bf16 approx err worst-case ~2)
#define NREG 128            // 64-centroid regions per token
#define CAP 256             // extras capacity per token

#define ASTAGE (128 * 128)              // 16KB
#define STAGE_BYTES (2 * ASTAGE)        // A + B = 32KB
#define SMEM_BYTES (NSTAGE * STAGE_BYTES) // 96KB dynamic

// ---------------------------------------------------------------------------
// Scratch (allocation-free: __device__ globals)
// ---------------------------------------------------------------------------
__device__ float g_cnorm[KCENT];
__device__ __align__(16) unsigned short gA1[(size_t)NTOK * DDIM];   // bf16(rep)
__device__ __align__(16) unsigned short gB1[(size_t)KCENT * DDIM];  // bf16(cent)
__device__ float g_pd[(size_t)NTOK * NREG];      // per-region approx min
__device__ int   g_pi[(size_t)NTOK * NREG];      // per-region approx argmin
__device__ int   g_cnt[NTOK];                    // extras counter
__device__ float g_cv[(size_t)NTOK * CAP];       // extras approx value
__device__ int   g_ci[(size_t)NTOK * CAP];       // extras index

// ---------------------------------------------------------------------------
// Helpers
// ---------------------------------------------------------------------------
__device__ __forceinline__ uint32_t smem_u32(const void* p) {
    uint32_t a;
    asm("{ .reg .u64 t; cvta.to.shared.u64 t, %1; cvt.u32.u64 %0, t; }" : "=r"(a) : "l"(p));
    return a;
}

// SW128 swizzle for (row, 16B-chunk) in a 128B-row buffer. chunk in 0..7.
__device__ __forceinline__ uint32_t swoff(int row, int chunk) {
    return (uint32_t)(row * 128 + ((chunk ^ (row & 7)) << 4));
}

#define CP_ASYNC16(dst, src) \
    asm volatile("cp.async.cg.shared.global [%0], [%1], 16;" :: "r"(dst), "l"(src) : "memory")
#define CP_COMMIT() asm volatile("cp.async.commit_group;" ::: "memory")
#define CP_WAIT(n)  asm volatile("cp.async.wait_group %0;" :: "n"(n) : "memory")

__device__ __forceinline__ void ldsm4(uint32_t* r, uint32_t addr) {
    asm volatile("ldmatrix.sync.aligned.m8n8.x4.shared.b16 {%0,%1,%2,%3}, [%4];"
                 : "=r"(r[0]), "=r"(r[1]), "=r"(r[2]), "=r"(r[3]) : "r"(addr));
}

__device__ __forceinline__ void mma16816(float* c, const uint32_t* a, const uint32_t* b) {
    asm volatile(
        "mma.sync.aligned.m16n8k16.row.col.f32.bf16.bf16.f32 "
        "{%0,%1,%2,%3}, {%4,%5,%6,%7}, {%8,%9}, {%0,%1,%2,%3};"
        : "+f"(c[0]), "+f"(c[1]), "+f"(c[2]), "+f"(c[3])
        : "r"(a[0]), "r"(a[1]), "r"(a[2]), "r"(a[3]), "r"(b[0]), "r"(b[1]));
}

// ---------------------------------------------------------------------------
// Init / conversion kernels
// ---------------------------------------------------------------------------
__global__ void zero_cnt() {
    g_cnt[blockIdx.x * 256 + threadIdx.x] = 0;
}

// rep (dropping t=0 rows) -> dense [4096 x 768] bf16
__global__ void conv_rep1(const float* __restrict__ rep) {
    int i = blockIdx.x * 256 + threadIdx.x;           // over NTOK*DDIM/4
    int row = i / (DDIM / 4);
    int c4  = i % (DDIM / 4);
    int srow = row + (row >> 9) + 1;                  // b*513 + t + 1
    float4 v = ((const float4*)rep)[(size_t)srow * (DDIM / 4) + c4];
    __nv_bfloat162 lo = __floats2bfloat162_rn(v.x, v.y);
    __nv_bfloat162 hi = __floats2bfloat162_rn(v.z, v.w);
    uint2 u;
    u.x = reinterpret_cast<uint32_t&>(lo);
    u.y = reinterpret_cast<uint32_t&>(hi);
    ((uint2*)gA1)[i] = u;
}

// centroids -> bf16, fused with fp32 squared-norm (one warp per centroid)
__global__ void conv_cent_norm(const float* __restrict__ cent) {
    int k = blockIdx.x * 8 + (threadIdx.x >> 5);
    int lane = threadIdx.x & 31;
    const float4* src = (const float4*)(cent + (size_t)k * DDIM);
    uint2* dst = (uint2*)(gB1 + (size_t)k * DDIM);
    float s = 0.f;
#pragma unroll
    for (int j = 0; j < 6; ++j) {                     // 6*32 = 192 float4 = 768
        int q = lane + 32 * j;
        float4 v = src[q];
        __nv_bfloat162 lo = __floats2bfloat162_rn(v.x, v.y);
        __nv_bfloat162 hi = __floats2bfloat162_rn(v.z, v.w);
        uint2 u;
        u.x = reinterpret_cast<uint32_t&>(lo);
        u.y = reinterpret_cast<uint32_t&>(hi);
        dst[q] = u;
        s += v.x * v.x + v.y * v.y + v.z * v.z + v.w * v.w;
    }
#pragma unroll
    for (int off = 16; off; off >>= 1) s += __shfl_down_sync(0xffffffffu, s, off);
    if (lane == 0) g_cnorm[k] = s;
}

// ---------------------------------------------------------------------------
// Phase 1: bf16 GEMM; epilogue emits per-region (min, argmin) + extras.
// Grid (32, 64), 256 threads. Warp grid 4(m) x 2(n): warp tile 32 x 64.
// BK=64, 3-stage cp.async pipeline, ONE __syncthreads per k-iter (12 total).
// ---------------------------------------------------------------------------
__global__ __launch_bounds__(256, 2) void vq_gemm() {
    extern __shared__ __align__(16) char smem[];
    const uint32_t sb = smem_u32(smem);

    const int tid  = threadIdx.x;
    const int wid  = tid >> 5;
    const int lane = tid & 31;
    const int warp_m = wid & 3;     // 4 rows of warps (32 rows each)
    const int warp_n = wid >> 2;    // 2 cols of warps (64 cols each)
    const int mBase = blockIdx.x * BM;
    const int nBase = blockIdx.y * BN;

    // Stage: A 128 rows x 8 chunks + B 128 rows x 8 chunks = 2048 x 16B.
    auto load_stage = [&](int k0, int st) {
        const uint32_t base = sb + st * STAGE_BYTES;
#pragma unroll
        for (int t = 0; t < 8; ++t) {
            int l = tid + t * 256;            // 0..2047
            int part = l >> 10;               // 0: A, 1: B
            int e = l & 1023;
            int row = e >> 3, ch = e & 7;
            const unsigned short* src = part
                ? &gB1[(size_t)(nBase + row) * DDIM + k0 + ch * 8]
                : &gA1[(size_t)(mBase + row) * DDIM + k0 + ch * 8];
            CP_ASYNC16(base + part * ASTAGE + swoff(row, ch), src);
        }
    };

    float acc[2][8][4];
#pragma unroll
    for (int mt = 0; mt < 2; ++mt)
#pragma unroll
        for (int nt = 0; nt < 8; ++nt)
#pragma unroll
            for (int i = 0; i < 4; ++i) acc[mt][nt][i] = 0.f;

    // ldmatrix lane address components (chunk = ks*2 + {aCh|bCh})
    const int aRow = warp_m * 32 + (lane & 15);          // + mt*16
    const int aCh  = lane >> 4;
    const int bRow = warp_n * 64 + (lane & 7) + ((lane >> 4) << 3);  // + nt2*16
    const int bCh  = (lane >> 3) & 1;

    load_stage(0, 0);  CP_COMMIT();
    load_stage(BK, 1); CP_COMMIT();

    for (int it = 0; it < KCHUNKS; ++it) {
        if (it + 1 < KCHUNKS) { CP_WAIT(1); } else { CP_WAIT(0); }
        __syncthreads();      // stage 'it' visible to all; stage it-1 fully consumed
        if (it + 2 < KCHUNKS) {
            load_stage((it + 2) * BK, (it + 2) % NSTAGE);
            CP_COMMIT();
        }
        const uint32_t stA = sb + (it % NSTAGE) * STAGE_BYTES;
        const uint32_t stB = stA + ASTAGE;

#pragma unroll
        for (int ks = 0; ks < 4; ++ks) {      // four k16 steps per 128B row
            uint32_t afr[2][4];
            uint32_t bfr[8][2];
#pragma unroll
            for (int mt = 0; mt < 2; ++mt)
                ldsm4(afr[mt], stA + swoff(aRow + mt * 16, ks * 2 + aCh));
#pragma unroll
            for (int nt2 = 0; nt2 < 4; ++nt2) {
                uint32_t r[4];
                ldsm4(r, stB + swoff(bRow + nt2 * 16, ks * 2 + bCh));
                bfr[nt2 * 2][0]     = r[0];
                bfr[nt2 * 2][1]     = r[1];
                bfr[nt2 * 2 + 1][0] = r[2];
                bfr[nt2 * 2 + 1][1] = r[3];
            }
#pragma unroll
            for (int mt = 0; mt < 2; ++mt)
#pragma unroll
                for (int nt = 0; nt < 8; ++nt)
                    mma16816(acc[mt][nt], afr[mt], bfr[nt]);
        }
    }

    // ---- Epilogue: per-row region min/argmin + extras within DELTA ----
    const int groupID = lane >> 2;
    const int tIdx    = lane & 3;
    const int colBase = nBase + warp_n * 64;
    const int region  = blockIdx.y * 2 + warp_n;

    float cn[8][2];
#pragma unroll
    for (int nt = 0; nt < 8; ++nt) {
        cn[nt][0] = __ldg(&g_cnorm[colBase + nt * 8 + tIdx * 2 + 0]);
        cn[nt][1] = __ldg(&g_cnorm[colBase + nt * 8 + tIdx * 2 + 1]);
    }

#pragma unroll
    for (int mt = 0; mt < 2; ++mt)
#pragma unroll
        for (int rh = 0; rh < 2; ++rh) {
            const int row = mBase + warp_m * 32 + mt * 16 + rh * 8 + groupID;
            float dv[8][2];
            float best = 3.4e38f;
            int bidx = 0;
#pragma unroll
            for (int nt = 0; nt < 8; ++nt)
#pragma unroll
                for (int jj = 0; jj < 2; ++jj) {
                    float d = cn[nt][jj] - 2.f * acc[mt][nt][rh * 2 + jj];
                    dv[nt][jj] = d;
                    int gi = colBase + nt * 8 + tIdx * 2 + jj;
                    if (d < best) { best = d; bidx = gi; }
                }
            // quad reduce (lanes groupID*4 + tIdx); all lanes converge
#pragma unroll
            for (int x = 1; x < 4; x <<= 1) {
                float od = __shfl_xor_sync(0xffffffffu, best, x);
                int   oi = __shfl_xor_sync(0xffffffffu, bidx, x);
                if (od < best || (od == best && oi < bidx)) { best = od; bidx = oi; }
            }
            if (tIdx == 0) {
                g_pd[(size_t)row * NREG + region] = best;
                g_pi[(size_t)row * NREG + region] = bidx;
            }
            // extras: values within DELTA of region min (excluding argmin)
            const float lim = best + DELTA;
#pragma unroll
            for (int nt = 0; nt < 8; ++nt)
#pragma unroll
                for (int jj = 0; jj < 2; ++jj) {
                    int gi = colBase + nt * 8 + tIdx * 2 + jj;
                    if (dv[nt][jj] <= lim && gi != bidx) {
                        int c = atomicAdd(&g_cnt[row], 1);
                        if (c < CAP) {
                            g_cv[(size_t)row * CAP + c] = dv[nt][jj];
                            g_ci[(size_t)row * CAP + c] = gi;
                        }
                    }
                }
        }
}

// ---------------------------------------------------------------------------
// Phase 2: per-token threshold + exact fp32 rescue + gather.
// One 128-thread block per token.
// Output layout: [tokens(4096) | quantized(4096*768)] float32.
// ---------------------------------------------------------------------------
#define MAXC 384
__global__ __launch_bounds__(128) void finalize(const float* __restrict__ rep,
                                                const float* __restrict__ cent,
                                                float* __restrict__ out) {
    __shared__ __align__(16) float srep[DDIM];
    __shared__ float wred[4];
    __shared__ float sthr;
    __shared__ int scand[MAXC];
    __shared__ int scn;
    __shared__ unsigned long long sbest;

    const int i = blockIdx.x;
    const int t = threadIdx.x;
    const int warpid = t >> 5;
    const int lane = t & 31;

    // rep row -> smem
    const int srow = i + (i >> 9) + 1;
    const float4* repv = (const float4*)(rep + (size_t)srow * DDIM);
#pragma unroll
    for (int q = 0; q < 2; ++q)
        if (t + q * 128 < DDIM / 4) ((float4*)srep)[t + q * 128] = repv[t + q * 128];
    if (t == 0) { scn = 0; sbest = ~0ull; }

    // dense region mins (coalesced: [token][region])
    const float dmin = g_pd[(size_t)i * NREG + t];
    float m = dmin;
#pragma unroll
    for (int off = 16; off; off >>= 1)
        m = fminf(m, __shfl_xor_sync(0xffffffffu, m, off));
    if (lane == 0) wred[warpid] = m;
    __syncthreads();
    if (t == 0) {
        float mm = fminf(fminf(wred[0], wred[1]), fminf(wred[2], wred[3]));
        sthr = mm + DELTA;
    }
    __syncthreads();
    const float thr = sthr;

    // collect candidates
    if (dmin <= thr) {
        int c = atomicAdd(&scn, 1);
        if (c < MAXC) scand[c] = g_pi[(size_t)i * NREG + t];
    }
    int ec = g_cnt[i];
    if (ec > CAP) ec = CAP;
    for (int e = t; e < ec; e += 128)
        if (g_cv[(size_t)i * CAP + e] <= thr) {
            int c = atomicAdd(&scn, 1);
            if (c < MAXC) scand[c] = g_ci[(size_t)i * CAP + e];
        }
    __syncthreads();

    // exact fp32 rescue, one candidate per warp round-robin
    int nc = scn < MAXC ? scn : MAXC;
    for (int c = warpid; c < nc; c += 4) {
        const int k = scand[c];
        const float4* c4 = (const float4*)(cent + (size_t)k * DDIM);
        float s0 = 0.f, s1 = 0.f, s2 = 0.f, s3 = 0.f;
#pragma unroll
        for (int q = lane; q < DDIM / 4; q += 32) {
            float4 cv = __ldg(&c4[q]);
            float4 rv = ((const float4*)srep)[q];
            s0 = fmaf(rv.x, cv.x, s0);
            s1 = fmaf(rv.y, cv.y, s1);
            s2 = fmaf(rv.z, cv.z, s2);
            s3 = fmaf(rv.w, cv.w, s3);
        }
        float s = (s0 + s1) + (s2 + s3);
#pragma unroll
        for (int off = 16; off; off >>= 1) s += __shfl_xor_sync(0xffffffffu, s, off);
        if (lane == 0) {
            float d = __ldg(&g_cnorm[k]) - 2.f * s;
            unsigned int u = __float_as_uint(d);
            unsigned int key = (u & 0x80000000u) ? ~u : (u | 0x80000000u);
            unsigned long long pk = ((unsigned long long)key << 32) | (unsigned int)k;
            atomicMin(&sbest, pk);
        }
    }
    __syncthreads();

    const int kbest = (int)(sbest & 0xffffffffu);
    if (t == 0) out[i] = (float)kbest;
    const float4* src = (const float4*)(cent + (size_t)kbest * DDIM);
    float4* dst = (float4*)(out + NTOK + (size_t)i * DDIM);
#pragma unroll
    for (int q = 0; q < 2; ++q)
        if (t + q * 128 < DDIM / 4) dst[t + q * 128] = src[t + q * 128];
}

// ---------------------------------------------------------------------------
extern "C" void kernel_launch(void* const* d_in, const int* in_sizes, int n_in,
                              void* d_out, int out_size) {
    const float* rep  = (const float*)d_in[0];   // [8,513,768]
    const float* cent = (const float*)d_in[1];   // [8192,768]
    float* out = (float*)d_out;

    cudaFuncSetAttribute(vq_gemm, cudaFuncAttributeMaxDynamicSharedMemorySize,
                         SMEM_BYTES);

    zero_cnt<<<NTOK / 256, 256>>>();
    conv_rep1<<<(size_t)NTOK * DDIM / 4 / 256, 256>>>(rep);
    conv_cent_norm<<<KCENT / 8, 256>>>(cent);

    dim3 g(NTOK / BM, KCENT / BN);
    vq_gemm<<<g, 256, SMEM_BYTES>>>();

    finalize<<<NTOK, 128>>>(rep, cent, out);
}

// round 11
// speedup vs baseline: 2.2084x; 1.0140x over previous
#include <cuda_runtime.h>
#include <cuda_bf16.h>
#include <cstdint>

// ---------------------------------------------------------------------------
// Problem constants
// ---------------------------------------------------------------------------
#define NTOK  4096          // 8 * 512 tokens (t=0 dropped)
#define DDIM  768
#define KCENT 8192

#define BM 128
#define BN 128
#define BK 64               // 64 bf16 = 128B rows (SW128)
#define KCHUNKS (DDIM / BK) // 12
#define NSTAGE 3
#define DELTA 8.0f          // prune threshold (bf16 approx err worst-case ~2)
#define NREG 128            // 64-centroid regions per token
#define CAP 256             // extras capacity per token

#define ASTAGE (128 * 128)              // 16KB
#define STAGE_BYTES (2 * ASTAGE)        // A + B = 32KB
#define SMEM_BYTES (NSTAGE * STAGE_BYTES) // 96KB dynamic

// ---------------------------------------------------------------------------
// Scratch (allocation-free: __device__ globals)
// ---------------------------------------------------------------------------
__device__ float g_cnorm[KCENT];
__device__ __align__(16) unsigned short gA1[(size_t)NTOK * DDIM];   // bf16(rep)
__device__ __align__(16) unsigned short gB1[(size_t)KCENT * DDIM];  // bf16(cent)
__device__ float g_pd[(size_t)NTOK * NREG];      // per-region approx min
__device__ int   g_pi[(size_t)NTOK * NREG];      // per-region approx argmin
__device__ int   g_cnt[NTOK];                    // extras counter
__device__ float g_cv[(size_t)NTOK * CAP];       // extras approx value
__device__ int   g_ci[(size_t)NTOK * CAP];       // extras index

// ---------------------------------------------------------------------------
// Helpers
// ---------------------------------------------------------------------------
__device__ __forceinline__ uint32_t smem_u32(const void* p) {
    uint32_t a;
    asm("{ .reg .u64 t; cvta.to.shared.u64 t, %1; cvt.u32.u64 %0, t; }" : "=r"(a) : "l"(p));
    return a;
}

// SW128 swizzle for (row, 16B-chunk) in a 128B-row buffer. chunk in 0..7.
__device__ __forceinline__ uint32_t swoff(int row, int chunk) {
    return (uint32_t)(row * 128 + ((chunk ^ (row & 7)) << 4));
}

#define CP_ASYNC16(dst, src) \
    asm volatile("cp.async.cg.shared.global [%0], [%1], 16;" :: "r"(dst), "l"(src) : "memory")
#define CP_COMMIT() asm volatile("cp.async.commit_group;" ::: "memory")
#define CP_WAIT(n)  asm volatile("cp.async.wait_group %0;" :: "n"(n) : "memory")

__device__ __forceinline__ void ldsm4(uint32_t* r, uint32_t addr) {
    asm volatile("ldmatrix.sync.aligned.m8n8.x4.shared.b16 {%0,%1,%2,%3}, [%4];"
                 : "=r"(r[0]), "=r"(r[1]), "=r"(r[2]), "=r"(r[3]) : "r"(addr));
}

__device__ __forceinline__ void mma16816(float* c, const uint32_t* a, const uint32_t* b) {
    asm volatile(
        "mma.sync.aligned.m16n8k16.row.col.f32.bf16.bf16.f32 "
        "{%0,%1,%2,%3}, {%4,%5,%6,%7}, {%8,%9}, {%0,%1,%2,%3};"
        : "+f"(c[0]), "+f"(c[1]), "+f"(c[2]), "+f"(c[3])
        : "r"(a[0]), "r"(a[1]), "r"(a[2]), "r"(a[3]), "r"(b[0]), "r"(b[1]));
}

// ---------------------------------------------------------------------------
// Conversion kernels
// ---------------------------------------------------------------------------
// rep (dropping t=0 rows) -> dense [4096 x 768] bf16; also zeroes g_cnt.
__global__ void conv_rep1(const float* __restrict__ rep) {
    int i = blockIdx.x * 256 + threadIdx.x;           // over NTOK*DDIM/4
    if (i < NTOK) g_cnt[i] = 0;
    int row = i / (DDIM / 4);
    int c4  = i % (DDIM / 4);
    int srow = row + (row >> 9) + 1;                  // b*513 + t + 1
    float4 v = ((const float4*)rep)[(size_t)srow * (DDIM / 4) + c4];
    __nv_bfloat162 lo = __floats2bfloat162_rn(v.x, v.y);
    __nv_bfloat162 hi = __floats2bfloat162_rn(v.z, v.w);
    uint2 u;
    u.x = reinterpret_cast<uint32_t&>(lo);
    u.y = reinterpret_cast<uint32_t&>(hi);
    ((uint2*)gA1)[i] = u;
}

// centroids -> bf16, fused with fp32 squared-norm (one warp per centroid)
__global__ void conv_cent_norm(const float* __restrict__ cent) {
    int k = blockIdx.x * 8 + (threadIdx.x >> 5);
    int lane = threadIdx.x & 31;
    const float4* src = (const float4*)(cent + (size_t)k * DDIM);
    uint2* dst = (uint2*)(gB1 + (size_t)k * DDIM);
    float s = 0.f;
#pragma unroll
    for (int j = 0; j < 6; ++j) {                     // 6*32 = 192 float4 = 768
        int q = lane + 32 * j;
        float4 v = src[q];
        __nv_bfloat162 lo = __floats2bfloat162_rn(v.x, v.y);
        __nv_bfloat162 hi = __floats2bfloat162_rn(v.z, v.w);
        uint2 u;
        u.x = reinterpret_cast<uint32_t&>(lo);
        u.y = reinterpret_cast<uint32_t&>(hi);
        dst[q] = u;
        s += v.x * v.x + v.y * v.y + v.z * v.z + v.w * v.w;
    }
#pragma unroll
    for (int off = 16; off; off >>= 1) s += __shfl_down_sync(0xffffffffu, s, off);
    if (lane == 0) g_cnorm[k] = s;
}

// ---------------------------------------------------------------------------
// Phase 1: bf16 GEMM; epilogue emits per-region (min, argmin) + extras.
// Grid (32, 64), 256 threads. Warp grid 4(m) x 2(n): warp tile 32 x 64.
// BK=64, 3-stage cp.async, 1 sync/iter, rotated fragment reloads (LDSM
// interleaved into the MMA stream to break WAR serialization).
// ---------------------------------------------------------------------------
__global__ __launch_bounds__(256, 2) void vq_gemm() {
    extern __shared__ __align__(16) char smem[];
    const uint32_t sb = smem_u32(smem);

    const int tid  = threadIdx.x;
    const int wid  = tid >> 5;
    const int lane = tid & 31;
    const int warp_m = wid & 3;     // 4 rows of warps (32 rows each)
    const int warp_n = wid >> 2;    // 2 cols of warps (64 cols each)
    const int mBase = blockIdx.x * BM;
    const int nBase = blockIdx.y * BN;

    // Stage: A 128 rows x 8 chunks + B 128 rows x 8 chunks = 2048 x 16B.
    auto load_stage = [&](int k0, int st) {
        const uint32_t base = sb + st * STAGE_BYTES;
#pragma unroll
        for (int t = 0; t < 8; ++t) {
            int l = tid + t * 256;            // 0..2047
            int part = l >> 10;               // 0: A, 1: B
            int e = l & 1023;
            int row = e >> 3, ch = e & 7;
            const unsigned short* src = part
                ? &gB1[(size_t)(nBase + row) * DDIM + k0 + ch * 8]
                : &gA1[(size_t)(mBase + row) * DDIM + k0 + ch * 8];
            CP_ASYNC16(base + part * ASTAGE + swoff(row, ch), src);
        }
    };

    float acc[2][8][4];
#pragma unroll
    for (int mt = 0; mt < 2; ++mt)
#pragma unroll
        for (int nt = 0; nt < 8; ++nt)
#pragma unroll
            for (int i = 0; i < 4; ++i) acc[mt][nt][i] = 0.f;

    // ldmatrix lane address components (chunk = ks*2 + {aCh|bCh})
    const int aRow = warp_m * 32 + (lane & 15);          // + mt*16
    const int aCh  = lane >> 4;
    const int bRow = warp_n * 64 + (lane & 7) + ((lane >> 4) << 3);  // + nt2*16
    const int bCh  = (lane >> 3) & 1;

    load_stage(0, 0);  CP_COMMIT();
    load_stage(BK, 1); CP_COMMIT();

    uint32_t afr[2][4];
    uint32_t bfr[8][2];

    auto loadA = [&](uint32_t stA, int ks) {
#pragma unroll
        for (int mt = 0; mt < 2; ++mt)
            ldsm4(afr[mt], stA + swoff(aRow + mt * 16, ks * 2 + aCh));
    };
    auto loadBpair = [&](uint32_t stB, int ks, int nt2) {
        uint32_t r[4];
        ldsm4(r, stB + swoff(bRow + nt2 * 16, ks * 2 + bCh));
        bfr[nt2 * 2][0]     = r[0];
        bfr[nt2 * 2][1]     = r[1];
        bfr[nt2 * 2 + 1][0] = r[2];
        bfr[nt2 * 2 + 1][1] = r[3];
    };

    for (int it = 0; it < KCHUNKS; ++it) {
        if (it + 1 < KCHUNKS) { CP_WAIT(1); } else { CP_WAIT(0); }
        __syncthreads();      // stage 'it' visible; stage it-1 fully consumed
        if (it + 2 < KCHUNKS) {
            load_stage((it + 2) * BK, (it + 2) % NSTAGE);
            CP_COMMIT();
        }
        const uint32_t stA = sb + (it % NSTAGE) * STAGE_BYTES;
        const uint32_t stB = stA + ASTAGE;

        // Preload ks=0 fragments
        loadA(stA, 0);
#pragma unroll
        for (int nt2 = 0; nt2 < 4; ++nt2) loadBpair(stB, 0, nt2);

#pragma unroll
        for (int ks = 0; ks < 4; ++ks) {
            const bool more = (ks < 3);
            // Consume bfr pair-by-pair; reload each pair for ks+1 right after
            // its last consumer (WAR resolved at issue order -> LDSM overlaps
            // the remaining MMA stream).
#pragma unroll
            for (int nt2 = 0; nt2 < 4; ++nt2) {
                mma16816(acc[0][nt2 * 2],     afr[0], bfr[nt2 * 2]);
                mma16816(acc[1][nt2 * 2],     afr[1], bfr[nt2 * 2]);
                mma16816(acc[0][nt2 * 2 + 1], afr[0], bfr[nt2 * 2 + 1]);
                mma16816(acc[1][nt2 * 2 + 1], afr[1], bfr[nt2 * 2 + 1]);
                if (more) loadBpair(stB, ks + 1, nt2);
            }
            if (more) loadA(stA, ks + 1);
        }
    }

    // ---- Epilogue: per-row region min/argmin + extras within DELTA ----
    const int groupID = lane >> 2;
    const int tIdx    = lane & 3;
    const int colBase = nBase + warp_n * 64;
    const int region  = blockIdx.y * 2 + warp_n;

    float cn[8][2];
#pragma unroll
    for (int nt = 0; nt < 8; ++nt) {
        cn[nt][0] = __ldg(&g_cnorm[colBase + nt * 8 + tIdx * 2 + 0]);
        cn[nt][1] = __ldg(&g_cnorm[colBase + nt * 8 + tIdx * 2 + 1]);
    }

#pragma unroll
    for (int mt = 0; mt < 2; ++mt)
#pragma unroll
        for (int rh = 0; rh < 2; ++rh) {
            const int row = mBase + warp_m * 32 + mt * 16 + rh * 8 + groupID;
            float dv[8][2];
            float best = 3.4e38f;
            int bidx = 0;
#pragma unroll
            for (int nt = 0; nt < 8; ++nt)
#pragma unroll
                for (int jj = 0; jj < 2; ++jj) {
                    float d = cn[nt][jj] - 2.f * acc[mt][nt][rh * 2 + jj];
                    dv[nt][jj] = d;
                    int gi = colBase + nt * 8 + tIdx * 2 + jj;
                    if (d < best) { best = d; bidx = gi; }
                }
            // quad reduce (lanes groupID*4 + tIdx); all lanes converge
#pragma unroll
            for (int x = 1; x < 4; x <<= 1) {
                float od = __shfl_xor_sync(0xffffffffu, best, x);
                int   oi = __shfl_xor_sync(0xffffffffu, bidx, x);
                if (od < best || (od == best && oi < bidx)) { best = od; bidx = oi; }
            }
            if (tIdx == 0) {
                g_pd[(size_t)row * NREG + region] = best;
                g_pi[(size_t)row * NREG + region] = bidx;
            }
            // extras: values within DELTA of region min (excluding argmin)
            const float lim = best + DELTA;
#pragma unroll
            for (int nt = 0; nt < 8; ++nt)
#pragma unroll
                for (int jj = 0; jj < 2; ++jj) {
                    int gi = colBase + nt * 8 + tIdx * 2 + jj;
                    if (dv[nt][jj] <= lim && gi != bidx) {
                        int c = atomicAdd(&g_cnt[row], 1);
                        if (c < CAP) {
                            g_cv[(size_t)row * CAP + c] = dv[nt][jj];
                            g_ci[(size_t)row * CAP + c] = gi;
                        }
                    }
                }
        }
}

// ---------------------------------------------------------------------------
// Phase 2: per-token threshold + exact fp32 rescue + gather.
// One 128-thread block per token.
// Output layout: [tokens(4096) | quantized(4096*768)] float32.
// ---------------------------------------------------------------------------
#define MAXC 384
__global__ __launch_bounds__(128) void finalize(const float* __restrict__ rep,
                                                const float* __restrict__ cent,
                                                float* __restrict__ out) {
    __shared__ __align__(16) float srep[DDIM];
    __shared__ float wred[4];
    __shared__ float sthr;
    __shared__ int scand[MAXC];
    __shared__ int scn;
    __shared__ unsigned long long sbest;

    const int i = blockIdx.x;
    const int t = threadIdx.x;
    const int warpid = t >> 5;
    const int lane = t & 31;

    // rep row -> smem
    const int srow = i + (i >> 9) + 1;
    const float4* repv = (const float4*)(rep + (size_t)srow * DDIM);
#pragma unroll
    for (int q = 0; q < 2; ++q)
        if (t + q * 128 < DDIM / 4) ((float4*)srep)[t + q * 128] = repv[t + q * 128];
    if (t == 0) { scn = 0; sbest = ~0ull; }

    // dense region mins (coalesced: [token][region])
    const float dmin = g_pd[(size_t)i * NREG + t];
    float m = dmin;
#pragma unroll
    for (int off = 16; off; off >>= 1)
        m = fminf(m, __shfl_xor_sync(0xffffffffu, m, off));
    if (lane == 0) wred[warpid] = m;
    __syncthreads();
    if (t == 0) {
        float mm = fminf(fminf(wred[0], wred[1]), fminf(wred[2], wred[3]));
        sthr = mm + DELTA;
    }
    __syncthreads();
    const float thr = sthr;

    // collect candidates
    if (dmin <= thr) {
        int c = atomicAdd(&scn, 1);
        if (c < MAXC) scand[c] = g_pi[(size_t)i * NREG + t];
    }
    int ec = g_cnt[i];
    if (ec > CAP) ec = CAP;
    for (int e = t; e < ec; e += 128)
        if (g_cv[(size_t)i * CAP + e] <= thr) {
            int c = atomicAdd(&scn, 1);
            if (c < MAXC) scand[c] = g_ci[(size_t)i * CAP + e];
        }
    __syncthreads();

    // exact fp32 rescue, one candidate per warp round-robin
    int nc = scn < MAXC ? scn : MAXC;
    for (int c = warpid; c < nc; c += 4) {
        const int k = scand[c];
        const float4* c4 = (const float4*)(cent + (size_t)k * DDIM);
        float s0 = 0.f, s1 = 0.f, s2 = 0.f, s3 = 0.f;
#pragma unroll
        for (int q = lane; q < DDIM / 4; q += 32) {
            float4 cv = __ldg(&c4[q]);
            float4 rv = ((const float4*)srep)[q];
            s0 = fmaf(rv.x, cv.x, s0);
            s1 = fmaf(rv.y, cv.y, s1);
            s2 = fmaf(rv.z, cv.z, s2);
            s3 = fmaf(rv.w, cv.w, s3);
        }
        float s = (s0 + s1) + (s2 + s3);
#pragma unroll
        for (int off = 16; off; off >>= 1) s += __shfl_xor_sync(0xffffffffu, s, off);
        if (lane == 0) {
            float d = __ldg(&g_cnorm[k]) - 2.f * s;
            unsigned int u = __float_as_uint(d);
            unsigned int key = (u & 0x80000000u) ? ~u : (u | 0x80000000u);
            unsigned long long pk = ((unsigned long long)key << 32) | (unsigned int)k;
            atomicMin(&sbest, pk);
        }
    }
    __syncthreads();

    const int kbest = (int)(sbest & 0xffffffffu);
    if (t == 0) out[i] = (float)kbest;
    const float4* src = (const float4*)(cent + (size_t)kbest * DDIM);
    float4* dst = (float4*)(out + NTOK + (size_t)i * DDIM);
#pragma unroll
    for (int q = 0; q < 2; ++q)
        if (t + q * 128 < DDIM / 4) dst[t + q * 128] = src[t + q * 128];
}

// ---------------------------------------------------------------------------
extern "C" void kernel_launch(void* const* d_in, const int* in_sizes, int n_in,
                              void* d_out, int out_size) {
    const float* rep  = (const float*)d_in[0];   // [8,513,768]
    const float* cent = (const float*)d_in[1];   // [8192,768]
    float* out = (float*)d_out;

    cudaFuncSetAttribute(vq_gemm, cudaFuncAttributeMaxDynamicSharedMemorySize,
                         SMEM_BYTES);

    conv_rep1<<<(size_t)NTOK * DDIM / 4 / 256, 256>>>(rep);
    conv_cent_norm<<<KCENT / 8, 256>>>(cent);

    dim3 g(NTOK / BM, KCENT / BN);
    vq_gemm<<<g, 256, SMEM_BYTES>>>();

    finalize<<<NTOK, 128>>>(rep, cent, out);
}

// round 12
// speedup vs baseline: 2.4568x; 1.1124x over previous
#include <cuda_runtime.h>
#include <cuda_fp16.h>
#include <cstdint>

// ---------------------------------------------------------------------------
// Problem constants
// ---------------------------------------------------------------------------
#define NTOK  4096          // 8 * 512 tokens (t=0 dropped)
#define DDIM  768
#define KCENT 8192

#define BM 128
#define BN 128
#define BK 64               // 64 fp16 = 128B rows (SW128)
#define KCHUNKS (DDIM / BK) // 12
#define NSTAGE 2
#define DELTA 8.0f          // prune threshold (fp16-acc err worst-case ~3.2)
#define NREG 128            // 64-centroid regions per token
#define CAP 256             // extras capacity per token

#define ASTAGE (128 * 128)              // 16KB
#define STAGE_BYTES (2 * ASTAGE)        // A + B = 32KB
#define SMEM_BYTES (NSTAGE * STAGE_BYTES) // 64KB dynamic -> 3 CTAs/SM

// ---------------------------------------------------------------------------
// Scratch (allocation-free: __device__ globals)
// ---------------------------------------------------------------------------
__device__ float g_cnorm[KCENT];
__device__ __align__(16) unsigned short gA1[(size_t)NTOK * DDIM];   // fp16(rep)
__device__ __align__(16) unsigned short gB1[(size_t)KCENT * DDIM];  // fp16(cent)
__device__ float g_pd[(size_t)NTOK * NREG];      // per-region approx min
__device__ int   g_pi[(size_t)NTOK * NREG];      // per-region approx argmin
__device__ int   g_cnt[NTOK];                    // extras counter
__device__ float g_cv[(size_t)NTOK * CAP];       // extras approx value
__device__ int   g_ci[(size_t)NTOK * CAP];       // extras index

// ---------------------------------------------------------------------------
// Helpers
// ---------------------------------------------------------------------------
__device__ __forceinline__ uint32_t smem_u32(const void* p) {
    uint32_t a;
    asm("{ .reg .u64 t; cvta.to.shared.u64 t, %1; cvt.u32.u64 %0, t; }" : "=r"(a) : "l"(p));
    return a;
}

// SW128 swizzle for (row, 16B-chunk) in a 128B-row buffer. chunk in 0..7.
__device__ __forceinline__ uint32_t swoff(int row, int chunk) {
    return (uint32_t)(row * 128 + ((chunk ^ (row & 7)) << 4));
}

#define CP_ASYNC16(dst, src) \
    asm volatile("cp.async.cg.shared.global [%0], [%1], 16;" :: "r"(dst), "l"(src) : "memory")
#define CP_COMMIT() asm volatile("cp.async.commit_group;" ::: "memory")
#define CP_WAIT(n)  asm volatile("cp.async.wait_group %0;" :: "n"(n) : "memory")

__device__ __forceinline__ void ldsm4(uint32_t* r, uint32_t addr) {
    asm volatile("ldmatrix.sync.aligned.m8n8.x4.shared.b16 {%0,%1,%2,%3}, [%4];"
                 : "=r"(r[0]), "=r"(r[1]), "=r"(r[2]), "=r"(r[3]) : "r"(addr));
}

// fp16 x fp16 -> fp16 accumulate (2-reg accumulator)
__device__ __forceinline__ void mma16816h(uint32_t* c, const uint32_t* a, const uint32_t* b) {
    asm volatile(
        "mma.sync.aligned.m16n8k16.row.col.f16.f16.f16.f16 "
        "{%0,%1}, {%2,%3,%4,%5}, {%6,%7}, {%0,%1};"
        : "+r"(c[0]), "+r"(c[1])
        : "r"(a[0]), "r"(a[1]), "r"(a[2]), "r"(a[3]), "r"(b[0]), "r"(b[1]));
}

// ---------------------------------------------------------------------------
// Conversion kernels
// ---------------------------------------------------------------------------
// rep (dropping t=0 rows) -> dense [4096 x 768] fp16; also zeroes g_cnt.
__global__ void conv_rep1(const float* __restrict__ rep) {
    int i = blockIdx.x * 256 + threadIdx.x;           // over NTOK*DDIM/4
    if (i < NTOK) g_cnt[i] = 0;
    int row = i / (DDIM / 4);
    int c4  = i % (DDIM / 4);
    int srow = row + (row >> 9) + 1;                  // b*513 + t + 1
    float4 v = ((const float4*)rep)[(size_t)srow * (DDIM / 4) + c4];
    __half2 lo = __floats2half2_rn(v.x, v.y);
    __half2 hi = __floats2half2_rn(v.z, v.w);
    uint2 u;
    u.x = reinterpret_cast<uint32_t&>(lo);
    u.y = reinterpret_cast<uint32_t&>(hi);
    ((uint2*)gA1)[i] = u;
}

// centroids -> fp16, fused with fp32 squared-norm (one warp per centroid)
__global__ void conv_cent_norm(const float* __restrict__ cent) {
    int k = blockIdx.x * 8 + (threadIdx.x >> 5);
    int lane = threadIdx.x & 31;
    const float4* src = (const float4*)(cent + (size_t)k * DDIM);
    uint2* dst = (uint2*)(gB1 + (size_t)k * DDIM);
    float s = 0.f;
#pragma unroll
    for (int j = 0; j < 6; ++j) {                     // 6*32 = 192 float4 = 768
        int q = lane + 32 * j;
        float4 v = src[q];
        __half2 lo = __floats2half2_rn(v.x, v.y);
        __half2 hi = __floats2half2_rn(v.z, v.w);
        uint2 u;
        u.x = reinterpret_cast<uint32_t&>(lo);
        u.y = reinterpret_cast<uint32_t&>(hi);
        dst[q] = u;
        s += v.x * v.x + v.y * v.y + v.z * v.z + v.w * v.w;
    }
#pragma unroll
    for (int off = 16; off; off >>= 1) s += __shfl_down_sync(0xffffffffu, s, off);
    if (lane == 0) g_cnorm[k] = s;
}

// ---------------------------------------------------------------------------
// Phase 1: fp16 GEMM (fp16 acc); epilogue emits per-region (min, argmin) + extras.
// Grid (32, 64), 256 threads. Warp grid 4(m) x 2(n): warp tile 32 x 64.
// BK=64, 2-stage cp.async, 1 sync/iter. 3 CTAs/SM target.
// ---------------------------------------------------------------------------
__global__ __launch_bounds__(256, 3) void vq_gemm() {
    extern __shared__ __align__(16) char smem[];
    const uint32_t sb = smem_u32(smem);

    const int tid  = threadIdx.x;
    const int wid  = tid >> 5;
    const int lane = tid & 31;
    const int warp_m = wid & 3;     // 4 rows of warps (32 rows each)
    const int warp_n = wid >> 2;    // 2 cols of warps (64 cols each)
    const int mBase = blockIdx.x * BM;
    const int nBase = blockIdx.y * BN;

    // Stage: A 128 rows x 8 chunks + B 128 rows x 8 chunks = 2048 x 16B.
    auto load_stage = [&](int k0, int st) {
        const uint32_t base = sb + st * STAGE_BYTES;
#pragma unroll
        for (int t = 0; t < 8; ++t) {
            int l = tid + t * 256;            // 0..2047
            int part = l >> 10;               // 0: A, 1: B
            int e = l & 1023;
            int row = e >> 3, ch = e & 7;
            const unsigned short* src = part
                ? &gB1[(size_t)(nBase + row) * DDIM + k0 + ch * 8]
                : &gA1[(size_t)(mBase + row) * DDIM + k0 + ch * 8];
            CP_ASYNC16(base + part * ASTAGE + swoff(row, ch), src);
        }
    };

    uint32_t acc[2][8][2];            // fp16x2 accumulators
#pragma unroll
    for (int mt = 0; mt < 2; ++mt)
#pragma unroll
        for (int nt = 0; nt < 8; ++nt) {
            acc[mt][nt][0] = 0u;
            acc[mt][nt][1] = 0u;
        }

    // ldmatrix lane address components (chunk = ks*2 + {aCh|bCh})
    const int aRow = warp_m * 32 + (lane & 15);          // + mt*16
    const int aCh  = lane >> 4;
    const int bRow = warp_n * 64 + (lane & 7) + ((lane >> 4) << 3);  // + nt2*16
    const int bCh  = (lane >> 3) & 1;

    load_stage(0, 0); CP_COMMIT();

    for (int it = 0; it < KCHUNKS; ++it) {
        CP_WAIT(0);           // current stage fully arrived (this thread's view)
        __syncthreads();      // all threads' loads visible; prev stage consumed
        if (it + 1 < KCHUNKS) {
            load_stage((it + 1) * BK, (it + 1) & 1);
            CP_COMMIT();
        }
        const uint32_t stA = sb + (it & 1) * STAGE_BYTES;
        const uint32_t stB = stA + ASTAGE;

#pragma unroll
        for (int ks = 0; ks < 4; ++ks) {      // four k16 steps per 128B row
            uint32_t afr[2][4];
            uint32_t bfr[8][2];
#pragma unroll
            for (int mt = 0; mt < 2; ++mt)
                ldsm4(afr[mt], stA + swoff(aRow + mt * 16, ks * 2 + aCh));
#pragma unroll
            for (int nt2 = 0; nt2 < 4; ++nt2) {
                uint32_t r[4];
                ldsm4(r, stB + swoff(bRow + nt2 * 16, ks * 2 + bCh));
                bfr[nt2 * 2][0]     = r[0];
                bfr[nt2 * 2][1]     = r[1];
                bfr[nt2 * 2 + 1][0] = r[2];
                bfr[nt2 * 2 + 1][1] = r[3];
            }
#pragma unroll
            for (int mt = 0; mt < 2; ++mt)
#pragma unroll
                for (int nt = 0; nt < 8; ++nt)
                    mma16816h(acc[mt][nt], afr[mt], bfr[nt]);
        }
    }

    // ---- Epilogue: per-row region min/argmin + extras within DELTA ----
    const int groupID = lane >> 2;
    const int tIdx    = lane & 3;
    const int colBase = nBase + warp_n * 64;
    const int region  = blockIdx.y * 2 + warp_n;

    float cn[8][2];
#pragma unroll
    for (int nt = 0; nt < 8; ++nt) {
        cn[nt][0] = __ldg(&g_cnorm[colBase + nt * 8 + tIdx * 2 + 0]);
        cn[nt][1] = __ldg(&g_cnorm[colBase + nt * 8 + tIdx * 2 + 1]);
    }

#pragma unroll
    for (int mt = 0; mt < 2; ++mt)
#pragma unroll
        for (int rh = 0; rh < 2; ++rh) {
            const int row = mBase + warp_m * 32 + mt * 16 + rh * 8 + groupID;
            float dv[8][2];
            float best = 3.4e38f;
            int bidx = 0;
#pragma unroll
            for (int nt = 0; nt < 8; ++nt) {
                float2 f = __half22float2(
                    reinterpret_cast<const __half2&>(acc[mt][nt][rh]));
#pragma unroll
                for (int jj = 0; jj < 2; ++jj) {
                    float d = cn[nt][jj] - 2.f * (jj ? f.y : f.x);
                    dv[nt][jj] = d;
                    int gi = colBase + nt * 8 + tIdx * 2 + jj;
                    if (d < best) { best = d; bidx = gi; }
                }
            }
            // quad reduce (lanes groupID*4 + tIdx); all lanes converge
#pragma unroll
            for (int x = 1; x < 4; x <<= 1) {
                float od = __shfl_xor_sync(0xffffffffu, best, x);
                int   oi = __shfl_xor_sync(0xffffffffu, bidx, x);
                if (od < best || (od == best && oi < bidx)) { best = od; bidx = oi; }
            }
            if (tIdx == 0) {
                g_pd[(size_t)row * NREG + region] = best;
                g_pi[(size_t)row * NREG + region] = bidx;
            }
            // extras: values within DELTA of region min (excluding argmin)
            const float lim = best + DELTA;
#pragma unroll
            for (int nt = 0; nt < 8; ++nt)
#pragma unroll
                for (int jj = 0; jj < 2; ++jj) {
                    int gi = colBase + nt * 8 + tIdx * 2 + jj;
                    if (dv[nt][jj] <= lim && gi != bidx) {
                        int c = atomicAdd(&g_cnt[row], 1);
                        if (c < CAP) {
                            g_cv[(size_t)row * CAP + c] = dv[nt][jj];
                            g_ci[(size_t)row * CAP + c] = gi;
                        }
                    }
                }
        }
}

// ---------------------------------------------------------------------------
// Phase 2: per-token threshold + exact fp32 rescue + gather.
// One 128-thread block per token.
// Output layout: [tokens(4096) | quantized(4096*768)] float32.
// ---------------------------------------------------------------------------
#define MAXC 384
__global__ __launch_bounds__(128) void finalize(const float* __restrict__ rep,
                                                const float* __restrict__ cent,
                                                float* __restrict__ out) {
    __shared__ __align__(16) float srep[DDIM];
    __shared__ float wred[4];
    __shared__ float sthr;
    __shared__ int scand[MAXC];
    __shared__ int scn;
    __shared__ unsigned long long sbest;

    const int i = blockIdx.x;
    const int t = threadIdx.x;
    const int warpid = t >> 5;
    const int lane = t & 31;

    // rep row -> smem
    const int srow = i + (i >> 9) + 1;
    const float4* repv = (const float4*)(rep + (size_t)srow * DDIM);
#pragma unroll
    for (int q = 0; q < 2; ++q)
        if (t + q * 128 < DDIM / 4) ((float4*)srep)[t + q * 128] = repv[t + q * 128];
    if (t == 0) { scn = 0; sbest = ~0ull; }

    // dense region mins (coalesced: [token][region])
    const float dmin = g_pd[(size_t)i * NREG + t];
    float m = dmin;
#pragma unroll
    for (int off = 16; off; off >>= 1)
        m = fminf(m, __shfl_xor_sync(0xffffffffu, m, off));
    if (lane == 0) wred[warpid] = m;
    __syncthreads();
    if (t == 0) {
        float mm = fminf(fminf(wred[0], wred[1]), fminf(wred[2], wred[3]));
        sthr = mm + DELTA;
    }
    __syncthreads();
    const float thr = sthr;

    // collect candidates
    if (dmin <= thr) {
        int c = atomicAdd(&scn, 1);
        if (c < MAXC) scand[c] = g_pi[(size_t)i * NREG + t];
    }
    int ec = g_cnt[i];
    if (ec > CAP) ec = CAP;
    for (int e = t; e < ec; e += 128)
        if (g_cv[(size_t)i * CAP + e] <= thr) {
            int c = atomicAdd(&scn, 1);
            if (c < MAXC) scand[c] = g_ci[(size_t)i * CAP + e];
        }
    __syncthreads();

    // exact fp32 rescue, one candidate per warp round-robin
    int nc = scn < MAXC ? scn : MAXC;
    for (int c = warpid; c < nc; c += 4) {
        const int k = scand[c];
        const float4* c4 = (const float4*)(cent + (size_t)k * DDIM);
        float s0 = 0.f, s1 = 0.f, s2 = 0.f, s3 = 0.f;
#pragma unroll
        for (int q = lane; q < DDIM / 4; q += 32) {
            float4 cv = __ldg(&c4[q]);
            float4 rv = ((const float4*)srep)[q];
            s0 = fmaf(rv.x, cv.x, s0);
            s1 = fmaf(rv.y, cv.y, s1);
            s2 = fmaf(rv.z, cv.z, s2);
            s3 = fmaf(rv.w, cv.w, s3);
        }
        float s = (s0 + s1) + (s2 + s3);
#pragma unroll
        for (int off = 16; off; off >>= 1) s += __shfl_xor_sync(0xffffffffu, s, off);
        if (lane == 0) {
            float d = __ldg(&g_cnorm[k]) - 2.f * s;
            unsigned int u = __float_as_uint(d);
            unsigned int key = (u & 0x80000000u) ? ~u : (u | 0x80000000u);
            unsigned long long pk = ((unsigned long long)key << 32) | (unsigned int)k;
            atomicMin(&sbest, pk);
        }
    }
    __syncthreads();

    const int kbest = (int)(sbest & 0xffffffffu);
    if (t == 0) out[i] = (float)kbest;
    const float4* src = (const float4*)(cent + (size_t)kbest * DDIM);
    float4* dst = (float4*)(out + NTOK + (size_t)i * DDIM);
#pragma unroll
    for (int q = 0; q < 2; ++q)
        if (t + q * 128 < DDIM / 4) dst[t + q * 128] = src[t + q * 128];
}

// ---------------------------------------------------------------------------
extern "C" void kernel_launch(void* const* d_in, const int* in_sizes, int n_in,
                              void* d_out, int out_size) {
    const float* rep  = (const float*)d_in[0];   // [8,513,768]
    const float* cent = (const float*)d_in[1];   // [8192,768]
    float* out = (float*)d_out;

    cudaFuncSetAttribute(vq_gemm, cudaFuncAttributeMaxDynamicSharedMemorySize,
                         SMEM_BYTES);

    conv_rep1<<<(size_t)NTOK * DDIM / 4 / 256, 256>>>(rep);
    conv_cent_norm<<<KCENT / 8, 256>>>(cent);

    dim3 g(NTOK / BM, KCENT / BN);
    vq_gemm<<<g, 256, SMEM_BYTES>>>();

    finalize<<<NTOK, 128>>>(rep, cent, out);
}